// round 7
// baseline (speedup 1.0000x reference)
#include <cuda_runtime.h>
#include <math.h>

#define B_ 8
#define N_ 9216
#define C_ 256
#define O_ 512
#define KS_ 16
#define CHK_ (N_/KS_)      // 576
#define LN_EPS 1e-5f

typedef unsigned int uint;

// ---------------- scratch ----------------------------------------------------
__device__ float  g_q  [B_*N_*C_];   // channel softmax of LN(x2)
__device__ float  g_qs [B_*N_];      // channel sum-exp per row
__device__ float2 g_st1[B_*N_];      // (mu, rsd) of x1 rows
__device__ float  g_S  [B_*C_];      // N-softmax denom per (b,d)
__device__ float  g_ctxp[(size_t)KS_*B_*C_*C_];
__device__ float  g_ctx[B_*C_*C_];
__device__ float  g_WA [B_*O_*C_];

// ---------------- fast exp (FMA only) ----------------------------------------
__device__ __forceinline__ float fexp(float x) {
    float t = fmaf(x, 1.4426950408889634f, 12582912.0f);
    float n = t - 12582912.0f;
    int ni = __float_as_int(t) - 0x4B400000;
    float r = fmaf(n, -0.693359375f, x);
    r = fmaf(n, 2.12194440e-4f, r);
    float z = r * r;
    float p = 1.9875691500E-4f;
    p = fmaf(p, r, 1.3981999507E-3f);
    p = fmaf(p, r, 8.3334519073E-3f);
    p = fmaf(p, r, 4.1665795894E-2f);
    p = fmaf(p, r, 1.6666665459E-1f);
    p = fmaf(p, r, 5.0000001201E-1f);
    float res = fmaf(z, p, r) + 1.0f;
    res = __int_as_float(__float_as_int(res) + (ni << 23));
    return (x > -80.0f) ? res : 0.0f;
}

// ---------------- tf32 helpers -----------------------------------------------
__device__ __forceinline__ uint tf32c(float f) {
    uint r;
    asm("cvt.rna.tf32.f32 %0, %1;" : "=r"(r) : "f"(f));
    return r;
}
__device__ __forceinline__ uint4 tf32c4(float4 v) {
    uint4 u;
    u.x = tf32c(v.x); u.y = tf32c(v.y); u.z = tf32c(v.z); u.w = tf32c(v.w);
    return u;
}
__device__ __forceinline__ void mma8(float4& d, const uint* a, const uint* b) {
    asm volatile("mma.sync.aligned.m16n8k8.row.col.f32.tf32.tf32.f32 "
        "{%0,%1,%2,%3}, {%4,%5,%6,%7}, {%8,%9}, {%0,%1,%2,%3};"
        : "+f"(d.x), "+f"(d.y), "+f"(d.z), "+f"(d.w)
        : "r"(a[0]), "r"(a[1]), "r"(a[2]), "r"(a[3]), "r"(b[0]), "r"(b[1]));
}

// ---------------- block reductions (256 threads) -----------------------------
__device__ __forceinline__ float blkSum(float v, float* sh) {
    #pragma unroll
    for (int o = 16; o > 0; o >>= 1) v += __shfl_down_sync(0xffffffffu, v, o);
    int w = threadIdx.x >> 5;
    if ((threadIdx.x & 31) == 0) sh[w] = v;
    __syncthreads();
    if (threadIdx.x < 32) {
        float x = (threadIdx.x < 8) ? sh[threadIdx.x] : 0.f;
        #pragma unroll
        for (int o = 4; o > 0; o >>= 1) x += __shfl_down_sync(0xffffffffu, x, o);
        if (threadIdx.x == 0) sh[0] = x;
    }
    __syncthreads();
    float r = sh[0];
    __syncthreads();
    return r;
}
__device__ __forceinline__ float blkMax(float v, float* sh) {
    #pragma unroll
    for (int o = 16; o > 0; o >>= 1) v = fmaxf(v, __shfl_xor_sync(0xffffffffu, v, o));
    int w = threadIdx.x >> 5;
    if ((threadIdx.x & 31) == 0) sh[w] = v;
    __syncthreads();
    if (threadIdx.x < 32) {
        float x = (threadIdx.x < 8) ? sh[threadIdx.x] : -INFINITY;
        #pragma unroll
        for (int o = 4; o > 0; o >>= 1) x = fmaxf(x, __shfl_xor_sync(0xffffffffu, x, o));
        if (threadIdx.x == 0) sh[0] = x;
    }
    __syncthreads();
    float r = sh[0];
    __syncthreads();
    return r;
}

// ---------------- stats of x1 rows (mu, rsd), warp per row -------------------
__global__ void stats_kernel(const float* __restrict__ x, float2* __restrict__ st) {
    int warp = threadIdx.x >> 5, lane = threadIdx.x & 31;
    size_t row = (size_t)blockIdx.x * 8 + warp;
    const float4* xr = (const float4*)(x + row * C_);
    float4 v0 = xr[lane], v1 = xr[lane + 32];
    float s  = v0.x + v0.y + v0.z + v0.w + v1.x + v1.y + v1.z + v1.w;
    float s2 = v0.x*v0.x + v0.y*v0.y + v0.z*v0.z + v0.w*v0.w
             + v1.x*v1.x + v1.y*v1.y + v1.z*v1.z + v1.w*v1.w;
    #pragma unroll
    for (int o = 16; o > 0; o >>= 1) {
        s  += __shfl_xor_sync(0xffffffffu, s, o);
        s2 += __shfl_xor_sync(0xffffffffu, s2, o);
    }
    float mu = s * (1.f / C_);
    float rsd = rsqrtf(s2 * (1.f / C_) - mu * mu + LN_EPS);
    if (lane == 0) st[row] = make_float2(mu, rsd);
}

// ---------------- q kernel: LN(x2) -> channel softmax + row sum --------------
__global__ void q_kernel(const float* __restrict__ x,
                         const float* __restrict__ w,
                         const float* __restrict__ b,
                         float* __restrict__ qout,
                         float* __restrict__ qs) {
    int warp = threadIdx.x >> 5, lane = threadIdx.x & 31;
    size_t row = (size_t)blockIdx.x * 8 + warp;
    const float4* xr = (const float4*)(x + row * C_);
    float4 v0 = xr[lane], v1 = xr[lane + 32];
    float s  = v0.x + v0.y + v0.z + v0.w + v1.x + v1.y + v1.z + v1.w;
    float s2 = v0.x*v0.x + v0.y*v0.y + v0.z*v0.z + v0.w*v0.w
             + v1.x*v1.x + v1.y*v1.y + v1.z*v1.z + v1.w*v1.w;
    #pragma unroll
    for (int o = 16; o > 0; o >>= 1) {
        s  += __shfl_xor_sync(0xffffffffu, s, o);
        s2 += __shfl_xor_sync(0xffffffffu, s2, o);
    }
    float mu = s * (1.f / C_);
    float rsd = rsqrtf(s2 * (1.f / C_) - mu * mu + LN_EPS);
    float4 w0 = ((const float4*)w)[lane], w1 = ((const float4*)w)[lane + 32];
    float4 b0 = ((const float4*)b)[lane], b1 = ((const float4*)b)[lane + 32];
    float4 e0, e1;
    e0.x = fexp((v0.x - mu) * rsd * w0.x + b0.x);
    e0.y = fexp((v0.y - mu) * rsd * w0.y + b0.y);
    e0.z = fexp((v0.z - mu) * rsd * w0.z + b0.z);
    e0.w = fexp((v0.w - mu) * rsd * w0.w + b0.w);
    e1.x = fexp((v1.x - mu) * rsd * w1.x + b1.x);
    e1.y = fexp((v1.y - mu) * rsd * w1.y + b1.y);
    e1.z = fexp((v1.z - mu) * rsd * w1.z + b1.z);
    e1.w = fexp((v1.w - mu) * rsd * w1.w + b1.w);
    float se = e0.x + e0.y + e0.z + e0.w + e1.x + e1.y + e1.z + e1.w;
    #pragma unroll
    for (int o = 16; o > 0; o >>= 1) se += __shfl_xor_sync(0xffffffffu, se, o);
    float inv = 1.f / se;
    e0.x *= inv; e0.y *= inv; e0.z *= inv; e0.w *= inv;
    e1.x *= inv; e1.y *= inv; e1.z *= inv; e1.w *= inv;
    float4* qr = (float4*)(qout + row * C_);
    qr[lane] = e0; qr[lane + 32] = e1;
    if (lane == 0) qs[row] = se;
}

// ---------------- zero S ------------------------------------------------------
__global__ void zero_kernel(float* __restrict__ p, int n) {
    int i = blockIdx.x * 256 + threadIdx.x;
    if (i < n) p[i] = 0.f;
}

// ---------------- context GEMM: double-buffered, fused LN + S accumulation ----
__global__ __launch_bounds__(256) void ctx_gemm(
        const float* __restrict__ qg, const float* __restrict__ qsg,
        const float* __restrict__ x1, const float2* __restrict__ st1,
        const float* __restrict__ w1, const float* __restrict__ b1,
        float* __restrict__ ctxp, float* __restrict__ Sg) {
    int bz = blockIdx.z;
    int b = bz / KS_, sk = bz % KS_;
    int m0 = blockIdx.y * 128, n0 = blockIdx.x * 128;
    const float*  A   = qg  + (size_t)b * N_ * C_;
    const float*  Bx  = x1  + (size_t)b * N_ * C_;
    const float*  qsb = qsg + (size_t)b * N_;
    const float2* stb = st1 + (size_t)b * N_;

    __shared__ uint sa[2][16][136];
    __shared__ uint sb[2][16][136];
    __shared__ float sW[128], sBb[128];

    int t = threadIdx.x;
    if (t < 128) { sW[t] = w1[n0 + t]; sBb[t] = b1[n0 + t]; }
    int warp = t >> 5, lane = t & 31, g = lane >> 2, tg = lane & 3;
    int wm = (warp >> 2) * 64, wn = (warp & 3) * 32;
    int kk0 = t >> 5, kk1 = 8 + (t >> 5), m4 = (t & 31) * 4;
    bool doS = (blockIdx.x == 0);
    int kbase = sk * CHK_;

    float4 acc[4][4];
    #pragma unroll
    for (int i = 0; i < 4; i++)
        #pragma unroll
        for (int j = 0; j < 4; j++) acc[i][j] = make_float4(0.f, 0.f, 0.f, 0.f);

    float4 a40, a41, b40, b41;
    float aq0, aq1;
    float2 s0, s1;
    float ssum[4] = {0.f, 0.f, 0.f, 0.f};

    auto LOAD = [&](int kt) {
        int r0 = kbase + kt * 16 + kk0, r1 = kbase + kt * 16 + kk1;
        a40 = *(const float4*)&A[(size_t)r0 * C_ + m0 + m4];
        a41 = *(const float4*)&A[(size_t)r1 * C_ + m0 + m4];
        aq0 = qsb[r0]; aq1 = qsb[r1];
        b40 = *(const float4*)&Bx[(size_t)r0 * C_ + n0 + m4];
        b41 = *(const float4*)&Bx[(size_t)r1 * C_ + n0 + m4];
        s0 = stb[r0]; s1 = stb[r1];
    };
    auto STORE = [&](int buf) {
        float4 ea0, ea1;
        ea0.x = a40.x * aq0; ea0.y = a40.y * aq0; ea0.z = a40.z * aq0; ea0.w = a40.w * aq0;
        ea1.x = a41.x * aq1; ea1.y = a41.y * aq1; ea1.z = a41.z * aq1; ea1.w = a41.w * aq1;
        if (doS) {
            ssum[0] += ea0.x + ea1.x; ssum[1] += ea0.y + ea1.y;
            ssum[2] += ea0.z + ea1.z; ssum[3] += ea0.w + ea1.w;
        }
        *(uint4*)&sa[buf][kk0][m4] = tf32c4(ea0);
        *(uint4*)&sa[buf][kk1][m4] = tf32c4(ea1);
        float wv0 = sW[m4], wv1 = sW[m4+1], wv2 = sW[m4+2], wv3 = sW[m4+3];
        float bv0 = sBb[m4], bv1 = sBb[m4+1], bv2 = sBb[m4+2], bv3 = sBb[m4+3];
        float4 l0, l1;
        l0.x = (b40.x - s0.x) * s0.y * wv0 + bv0;
        l0.y = (b40.y - s0.x) * s0.y * wv1 + bv1;
        l0.z = (b40.z - s0.x) * s0.y * wv2 + bv2;
        l0.w = (b40.w - s0.x) * s0.y * wv3 + bv3;
        l1.x = (b41.x - s1.x) * s1.y * wv0 + bv0;
        l1.y = (b41.y - s1.x) * s1.y * wv1 + bv1;
        l1.z = (b41.z - s1.x) * s1.y * wv2 + bv2;
        l1.w = (b41.w - s1.x) * s1.y * wv3 + bv3;
        *(uint4*)&sb[buf][kk0][m4] = tf32c4(l0);
        *(uint4*)&sb[buf][kk1][m4] = tf32c4(l1);
    };

    LOAD(0);
    __syncthreads();   // sW/sBb ready
    STORE(0);
    __syncthreads();

    const int NT = CHK_ / 16;
    for (int kt = 0; kt < NT; kt++) {
        int cur = kt & 1;
        bool last = (kt == NT - 1);
        if (!last) LOAD(kt + 1);
        #pragma unroll
        for (int ks = 0; ks < 16; ks += 8) {
            uint afr[4][4], bfr[4][2];
            #pragma unroll
            for (int mt = 0; mt < 4; mt++) {
                int m = wm + mt * 16 + g;
                afr[mt][0] = sa[cur][ks + tg][m];
                afr[mt][1] = sa[cur][ks + tg][m + 8];
                afr[mt][2] = sa[cur][ks + tg + 4][m];
                afr[mt][3] = sa[cur][ks + tg + 4][m + 8];
            }
            #pragma unroll
            for (int nt = 0; nt < 4; nt++) {
                int n = wn + nt * 8 + g;
                bfr[nt][0] = sb[cur][ks + tg][n];
                bfr[nt][1] = sb[cur][ks + tg + 4][n];
            }
            #pragma unroll
            for (int mt = 0; mt < 4; mt++)
                #pragma unroll
                for (int nt = 0; nt < 4; nt++)
                    mma8(acc[mt][nt], afr[mt], bfr[nt]);
        }
        if (!last) STORE(cur ^ 1);
        __syncthreads();
    }

    float* dst = ctxp + ((size_t)sk * B_ + b) * C_ * C_;
    #pragma unroll
    for (int mt = 0; mt < 4; mt++) {
        int row = m0 + wm + mt * 16 + g;
        #pragma unroll
        for (int nt = 0; nt < 4; nt++) {
            int col = n0 + wn + nt * 8 + tg * 2;
            *(float2*)&dst[(size_t)row * C_ + col] = make_float2(acc[mt][nt].x, acc[mt][nt].y);
            *(float2*)&dst[(size_t)(row + 8) * C_ + col] = make_float2(acc[mt][nt].z, acc[mt][nt].w);
        }
    }
    if (doS) {
        #pragma unroll
        for (int j = 0; j < 4; j++)
            atomicAdd(&Sg[b * C_ + m0 + m4 + j], ssum[j]);
    }
}

// ---------------- combined 4-way top-k masked softmax ------------------------
__global__ void topk_kernel(const float* __restrict__ ctxp, float* __restrict__ ctx,
                            const float* __restrict__ aw, const float* __restrict__ Sg) {
    __shared__ float sc[C_];
    __shared__ float sh[8];
    int row = blockIdx.x;
    int b = row >> 8, d = row & 255;
    int t = threadIdx.x;
    float v = 0.f;
    #pragma unroll
    for (int sk = 0; sk < KS_; sk++)
        v += ctxp[(((size_t)sk * B_ + b) * C_ + d) * C_ + t];
    v /= Sg[row];
    sc[t] = v;
    __syncthreads();
    int rank = 0;
    #pragma unroll 8
    for (int f = 0; f < C_; f++) {
        float vf = sc[f];
        rank += (vf > v) || (vf == v && f < t);
    }
    float m = blkMax(v, sh);
    float e = fexp(v - m);
    float z1 = blkSum(rank < 128 ? e : 0.f, sh);
    float z2 = blkSum(rank < 170 ? e : 0.f, sh);
    float z3 = blkSum(rank < 192 ? e : 0.f, sh);
    float z4 = blkSum(rank < 204 ? e : 0.f, sh);
    float coeff = 0.f;
    if (rank < 128) coeff += aw[0] / z1;
    if (rank < 170) coeff += aw[1] / z2;
    if (rank < 192) coeff += aw[2] / z3;
    if (rank < 204) coeff += aw[3] / z4;
    ctx[(size_t)row * C_ + t] = e * coeff;
}

// ---------------- small GEMM (F1): WA = reproj_w @ A -------------------------
__global__ void gemm64(const float* __restrict__ A, const float* __restrict__ B,
                       float* __restrict__ C,
                       int K, size_t sA, size_t sB, size_t sC,
                       int lda, int ldb, int ldc) {
    int bz = blockIdx.z;
    const float* Ab = A + (size_t)bz * sA;
    const float* Bb = B + (size_t)bz * sB;
    float* Cb = C + (size_t)bz * sC;
    int m0 = blockIdx.y * 64, n0 = blockIdx.x * 64;
    __shared__ float sa[16][65];
    __shared__ float sb[16][64];
    int t = threadIdx.x;
    int tx = t % 16, ty = t / 16;
    int r_ld = t / 16, kk_lda = t % 16;
    int c_ld = t % 64, kk_ldb = t / 64;
    float acc[4][4] = {};
    for (int k0 = 0; k0 < K; k0 += 16) {
        __syncthreads();
        #pragma unroll
        for (int it = 0; it < 4; it++) {
            sa[kk_lda][r_ld + 16 * it] = Ab[(size_t)(m0 + r_ld + 16 * it) * lda + k0 + kk_lda];
            sb[kk_ldb + 4 * it][c_ld] = Bb[(size_t)(k0 + kk_ldb + 4 * it) * ldb + n0 + c_ld];
        }
        __syncthreads();
        #pragma unroll
        for (int kk = 0; kk < 16; kk++) {
            float av[4], bv[4];
            #pragma unroll
            for (int i = 0; i < 4; i++) av[i] = sa[kk][ty + 16 * i];
            #pragma unroll
            for (int j = 0; j < 4; j++) bv[j] = sb[kk][tx + 16 * j];
            #pragma unroll
            for (int i = 0; i < 4; i++)
                #pragma unroll
                for (int j = 0; j < 4; j++) acc[i][j] = fmaf(av[i], bv[j], acc[i][j]);
        }
    }
    #pragma unroll
    for (int i = 0; i < 4; i++)
        #pragma unroll
        for (int j = 0; j < 4; j++)
            Cb[(size_t)(m0 + ty + 16 * i) * ldc + n0 + tx + 16 * j] = acc[i][j];
}

// ---------------- final: rp = q @ WA^T (double-buffered, dyn smem) -----------
#define SQW 12
#define BUFW ((64 + 512) * SQW)        // 6912 words per buffer
#define POOLW (2 * BUFW)               // 13824 words = 55296 B (dynamic)
__global__ __launch_bounds__(512) void final_kernel(
        const float* __restrict__ q, const float* __restrict__ WA,
        const float* __restrict__ rbias, const float* __restrict__ w2g,
        const float* __restrict__ b2g, float* __restrict__ out) {
    extern __shared__ __align__(16) uint pool[];

    int bb = blockIdx.y;
    int n0 = blockIdx.x * 64;
    const float* qb  = q  + (size_t)bb * N_ * C_;
    const float* WAb = WA + (size_t)bb * O_ * C_;

    int t = threadIdx.x, warp = t >> 5, lane = t & 31, g = lane >> 2, tg = lane & 3;
    int o0 = warp * 32;

    int rq = t >> 1, kgq = (t & 1) * 4;          // q loader (t<128)
    int ow0 = t >> 1, kgw0 = (t & 1) * 4;        // WA loader slot 0
    int ow1 = (t + 512) >> 1, kgw1 = ((t + 512) & 1) * 4;

    float4 acc[4][4];
    #pragma unroll
    for (int i = 0; i < 4; i++)
        #pragma unroll
        for (int j = 0; j < 4; j++) acc[i][j] = make_float4(0.f, 0.f, 0.f, 0.f);

    float4 pq, pw0, pw1;
    auto LOAD = [&](int k0) {
        if (t < 128) pq = *(const float4*)&qb[(size_t)(n0 + rq) * C_ + k0 + kgq];
        pw0 = *(const float4*)&WAb[(size_t)ow0 * C_ + k0 + kgw0];
        pw1 = *(const float4*)&WAb[(size_t)ow1 * C_ + k0 + kgw1];
    };
    auto STORE = [&](int buf) {
        uint* sq  = pool + buf * BUFW;
        uint* swa = pool + buf * BUFW + 64 * SQW;
        if (t < 128) *(uint4*)&sq[rq * SQW + kgq] = tf32c4(pq);
        *(uint4*)&swa[ow0 * SQW + kgw0] = tf32c4(pw0);
        *(uint4*)&swa[ow1 * SQW + kgw1] = tf32c4(pw1);
    };

    LOAD(0); STORE(0);
    __syncthreads();

    const int NT = C_ / 8;     // 32 stages
    for (int kt = 0; kt < NT; kt++) {
        int cur = kt & 1;
        bool last = (kt == NT - 1);
        if (!last) LOAD((kt + 1) * 8);
        uint* sq  = pool + cur * BUFW;
        uint* swa = pool + cur * BUFW + 64 * SQW;
        uint afr[4][4], bfr[4][2];
        #pragma unroll
        for (int mt = 0; mt < 4; mt++) {
            int r1 = mt * 16 + g;
            afr[mt][0] = sq[r1 * SQW + tg];
            afr[mt][1] = sq[(r1 + 8) * SQW + tg];
            afr[mt][2] = sq[r1 * SQW + tg + 4];
            afr[mt][3] = sq[(r1 + 8) * SQW + tg + 4];
        }
        #pragma unroll
        for (int nt = 0; nt < 4; nt++) {
            int o = o0 + nt * 8 + g;
            bfr[nt][0] = swa[o * SQW + tg];
            bfr[nt][1] = swa[o * SQW + tg + 4];
        }
        #pragma unroll
        for (int mt = 0; mt < 4; mt++)
            #pragma unroll
            for (int nt = 0; nt < 4; nt++)
                mma8(acc[mt][nt], afr[mt], bfr[nt]);
        if (!last) STORE(cur ^ 1);
        __syncthreads();
    }

    // ---- epilogue (pool reused) ----
    float* redS = (float*)pool;            // [16][64]
    float* redQ = (float*)(pool + 1024);   // [16][64]
    float* muS  = (float*)(pool + 2048);   // [64]
    float* rsS  = (float*)(pool + 2112);   // [64]
    float* sout = (float*)(pool + 2176);   // [128][68]

    // bias
    #pragma unroll
    for (int nt = 0; nt < 4; nt++) {
        int o = o0 + nt * 8 + tg * 2;
        float2 rb = *(const float2*)&rbias[o];
        #pragma unroll
        for (int mt = 0; mt < 4; mt++) {
            acc[mt][nt].x += rb.x; acc[mt][nt].y += rb.y;
            acc[mt][nt].z += rb.x; acc[mt][nt].w += rb.y;
        }
    }

    // LN stats
    #pragma unroll
    for (int mt = 0; mt < 4; mt++) {
        float sA = 0.f, qA = 0.f, sB = 0.f, qB = 0.f;
        #pragma unroll
        for (int nt = 0; nt < 4; nt++) {
            float4 a = acc[mt][nt];
            sA += a.x + a.y; qA += a.x * a.x + a.y * a.y;
            sB += a.z + a.w; qB += a.z * a.z + a.w * a.w;
        }
        #pragma unroll
        for (int o = 1; o <= 2; o <<= 1) {
            sA += __shfl_xor_sync(0xffffffffu, sA, o);
            qA += __shfl_xor_sync(0xffffffffu, qA, o);
            sB += __shfl_xor_sync(0xffffffffu, sB, o);
            qB += __shfl_xor_sync(0xffffffffu, qB, o);
        }
        if (tg == 0) {
            redS[warp * 64 + mt * 16 + g] = sA;
            redQ[warp * 64 + mt * 16 + g] = qA;
            redS[warp * 64 + mt * 16 + g + 8] = sB;
            redQ[warp * 64 + mt * 16 + g + 8] = qB;
        }
    }
    __syncthreads();
    if (t < 64) {
        float s = 0.f, qq = 0.f;
        #pragma unroll
        for (int w = 0; w < 16; w++) { s += redS[w * 64 + t]; qq += redQ[w * 64 + t]; }
        float mu = s * (1.f / O_);
        float var = qq * (1.f / O_) - mu * mu;
        muS[t] = mu;
        rsS[t] = rsqrtf(var + LN_EPS);
    }
    __syncthreads();
    float mu1[4], rs1[4], mu2[4], rs2[4];
    #pragma unroll
    for (int mt = 0; mt < 4; mt++) {
        mu1[mt] = muS[mt * 16 + g];     rs1[mt] = rsS[mt * 16 + g];
        mu2[mt] = muS[mt * 16 + g + 8]; rs2[mt] = rsS[mt * 16 + g + 8];
    }
    __syncthreads();

    #pragma unroll
    for (int p = 0; p < 4; p++) {
        if ((warp >> 2) == p) {
            int obase = (warp & 3) * 32;
            #pragma unroll
            for (int nt = 0; nt < 4; nt++) {
                int ol = obase + nt * 8 + tg * 2;
                int o = p * 128 + ol;
                float2 wv = *(const float2*)&w2g[o];
                float2 bv = *(const float2*)&b2g[o];
                #pragma unroll
                for (int mt = 0; mt < 4; mt++) {
                    int r1 = mt * 16 + g, r2 = r1 + 8;
                    float4 a = acc[mt][nt];
                    sout[ol * 68 + r1]       = (a.x - mu1[mt]) * rs1[mt] * wv.x + bv.x;
                    sout[(ol + 1) * 68 + r1] = (a.y - mu1[mt]) * rs1[mt] * wv.y + bv.y;
                    sout[ol * 68 + r2]       = (a.z - mu2[mt]) * rs2[mt] * wv.x + bv.x;
                    sout[(ol + 1) * 68 + r2] = (a.w - mu2[mt]) * rs2[mt] * wv.y + bv.y;
                }
            }
        }
        __syncthreads();
        #pragma unroll
        for (int i = 0; i < 4; i++) {
            int idx = t + 512 * i;
            int ol = idx >> 4, nn = (idx & 15) * 4;
            float4 v = *(float4*)&sout[ol * 68 + nn];
            *(float4*)&out[((size_t)bb * O_ + p * 128 + ol) * N_ + n0 + nn] = v;
        }
        __syncthreads();
    }
}

// ---------------- launch -----------------------------------------------------
extern "C" void kernel_launch(void* const* d_in, const int* in_sizes, int n_in,
                              void* d_out, int out_size) {
    const float* x1       = (const float*)d_in[0];
    const float* x2       = (const float*)d_in[1];
    const float* norm1_w  = (const float*)d_in[2];
    const float* norm1_b  = (const float*)d_in[3];
    const float* reproj_w = (const float*)d_in[4];
    const float* reproj_b = (const float*)d_in[5];
    const float* norm2_w  = (const float*)d_in[6];
    const float* norm2_b  = (const float*)d_in[7];
    const float* attn_w   = (const float*)d_in[8];
    float* out = (float*)d_out;

    float *q, *qs, *S, *ctxp, *ctx, *WA;
    float2* st1;
    cudaGetSymbolAddress((void**)&q,    g_q);
    cudaGetSymbolAddress((void**)&qs,   g_qs);
    cudaGetSymbolAddress((void**)&st1,  g_st1);
    cudaGetSymbolAddress((void**)&S,    g_S);
    cudaGetSymbolAddress((void**)&ctxp, g_ctxp);
    cudaGetSymbolAddress((void**)&ctx,  g_ctx);
    cudaGetSymbolAddress((void**)&WA,   g_WA);

    // raise dynamic smem limit for final_kernel (idempotent; not a stream op)
    cudaFuncSetAttribute(final_kernel,
                         cudaFuncAttributeMaxDynamicSharedMemorySize,
                         POOLW * 4);

    stats_kernel<<<B_ * N_ / 8, 256>>>(x1, st1);
    q_kernel<<<B_ * N_ / 8, 256>>>(x2, norm1_w, norm1_b, q, qs);
    zero_kernel<<<(B_ * C_ + 255) / 256, 256>>>(S, B_ * C_);

    ctx_gemm<<<dim3(2, 2, B_ * KS_), 256>>>(q, qs, x1, st1, norm1_w, norm1_b, ctxp, S);

    topk_kernel<<<B_ * C_, 256>>>(ctxp, ctx, attn_w, S);

    gemm64<<<dim3(C_ / 64, O_ / 64, B_), 256>>>(
        reproj_w, ctx, WA, C_,
        (size_t)0, (size_t)C_ * C_, (size_t)O_ * C_,
        C_, C_, C_);

    final_kernel<<<dim3(N_ / 64, B_), 512, POOLW * 4>>>(
        q, WA, reproj_b, norm2_w, norm2_b, out);
}

// round 10
// speedup vs baseline: 1.0079x; 1.0079x over previous
#include <cuda_runtime.h>
#include <math.h>

#define B_ 8
#define N_ 9216
#define C_ 256
#define O_ 512
#define KS_ 16
#define CHK_ (N_/KS_)      // 576
#define NCH_ 36
#define CR_ 256
#define LN_EPS 1e-5f

typedef unsigned int uint;

// ---------------- scratch ----------------------------------------------------
__device__ float  g_q  [B_*N_*C_];   // tf32-rounded channel softmax of LN(x2)
__device__ float  g_qe [B_*N_*C_];   // tf32-rounded unnormalized exp
__device__ float  g_n1 [B_*N_*C_];   // tf32-rounded LN(x1)
__device__ float  g_S  [B_*C_];      // N-softmax denom per (b,d)
__device__ float  g_ctxp[(size_t)KS_*B_*C_*C_];
__device__ float  g_ctx[B_*C_*C_];
__device__ float  g_WA [B_*O_*C_];   // tf32-rounded

// ---------------- fast exp (FMA only) ----------------------------------------
__device__ __forceinline__ float fexp(float x) {
    float t = fmaf(x, 1.4426950408889634f, 12582912.0f);
    float n = t - 12582912.0f;
    int ni = __float_as_int(t) - 0x4B400000;
    float r = fmaf(n, -0.693359375f, x);
    r = fmaf(n, 2.12194440e-4f, r);
    float z = r * r;
    float p = 1.9875691500E-4f;
    p = fmaf(p, r, 1.3981999507E-3f);
    p = fmaf(p, r, 8.3334519073E-3f);
    p = fmaf(p, r, 4.1665795894E-2f);
    p = fmaf(p, r, 1.6666665459E-1f);
    p = fmaf(p, r, 5.0000001201E-1f);
    float res = fmaf(z, p, r) + 1.0f;
    res = __int_as_float(__float_as_int(res) + (ni << 23));
    return (x > -80.0f) ? res : 0.0f;
}

// ---------------- tf32 helpers -----------------------------------------------
__device__ __forceinline__ uint tf32c(float f) {
    uint r;
    asm("cvt.rna.tf32.f32 %0, %1;" : "=r"(r) : "f"(f));
    return r;
}
__device__ __forceinline__ float tf32f(float f) { return __uint_as_float(tf32c(f)); }
__device__ __forceinline__ void mma8(float4& d, const uint* a, const uint* b) {
    asm volatile("mma.sync.aligned.m16n8k8.row.col.f32.tf32.tf32.f32 "
        "{%0,%1,%2,%3}, {%4,%5,%6,%7}, {%8,%9}, {%0,%1,%2,%3};"
        : "+f"(d.x), "+f"(d.y), "+f"(d.z), "+f"(d.w)
        : "r"(a[0]), "r"(a[1]), "r"(a[2]), "r"(a[3]), "r"(b[0]), "r"(b[1]));
}
__device__ __forceinline__ uint smem_u32(const void* p) {
    uint a;
    asm("{ .reg .u64 t; cvta.to.shared.u64 t, %1; cvt.u32.u64 %0, t; }"
        : "=r"(a) : "l"(p));
    return a;
}
__device__ __forceinline__ void cp16(uint dst, const void* src) {
    asm volatile("cp.async.cg.shared.global [%0], [%1], 16;"
                 :: "r"(dst), "l"(src) : "memory");
}
#define CP_COMMIT() asm volatile("cp.async.commit_group;" ::: "memory")
#define CP_WAIT1()  asm volatile("cp.async.wait_group 1;" ::: "memory")
#define CP_WAIT0()  asm volatile("cp.async.wait_group 0;" ::: "memory")

// ---------------- block reductions (256 threads) -----------------------------
__device__ __forceinline__ float blkSum(float v, float* sh) {
    #pragma unroll
    for (int o = 16; o > 0; o >>= 1) v += __shfl_down_sync(0xffffffffu, v, o);
    int w = threadIdx.x >> 5;
    if ((threadIdx.x & 31) == 0) sh[w] = v;
    __syncthreads();
    if (threadIdx.x < 32) {
        float x = (threadIdx.x < 8) ? sh[threadIdx.x] : 0.f;
        #pragma unroll
        for (int o = 4; o > 0; o >>= 1) x += __shfl_down_sync(0xffffffffu, x, o);
        if (threadIdx.x == 0) sh[0] = x;
    }
    __syncthreads();
    float r = sh[0];
    __syncthreads();
    return r;
}
__device__ __forceinline__ float blkMax(float v, float* sh) {
    #pragma unroll
    for (int o = 16; o > 0; o >>= 1) v = fmaxf(v, __shfl_xor_sync(0xffffffffu, v, o));
    int w = threadIdx.x >> 5;
    if ((threadIdx.x & 31) == 0) sh[w] = v;
    __syncthreads();
    if (threadIdx.x < 32) {
        float x = (threadIdx.x < 8) ? sh[threadIdx.x] : -INFINITY;
        #pragma unroll
        for (int o = 4; o > 0; o >>= 1) x = fmaxf(x, __shfl_xor_sync(0xffffffffu, x, o));
        if (threadIdx.x == 0) sh[0] = x;
    }
    __syncthreads();
    float r = sh[0];
    __syncthreads();
    return r;
}

// ---------------- ln1: n1 = tf32(LN(x1)), warp per row ------------------------
__global__ void ln1_kernel(const float* __restrict__ x,
                           const float* __restrict__ w,
                           const float* __restrict__ b,
                           float* __restrict__ n1) {
    int warp = threadIdx.x >> 5, lane = threadIdx.x & 31;
    size_t row = (size_t)blockIdx.x * 8 + warp;
    const float4* xr = (const float4*)(x + row * C_);
    float4 v0 = xr[lane], v1 = xr[lane + 32];
    float s  = v0.x + v0.y + v0.z + v0.w + v1.x + v1.y + v1.z + v1.w;
    float s2 = v0.x*v0.x + v0.y*v0.y + v0.z*v0.z + v0.w*v0.w
             + v1.x*v1.x + v1.y*v1.y + v1.z*v1.z + v1.w*v1.w;
    #pragma unroll
    for (int o = 16; o > 0; o >>= 1) {
        s  += __shfl_xor_sync(0xffffffffu, s, o);
        s2 += __shfl_xor_sync(0xffffffffu, s2, o);
    }
    float mu = s * (1.f / C_);
    float rsd = rsqrtf(s2 * (1.f / C_) - mu * mu + LN_EPS);
    float4 w0 = ((const float4*)w)[lane], w1 = ((const float4*)w)[lane + 32];
    float4 b0 = ((const float4*)b)[lane], b1 = ((const float4*)b)[lane + 32];
    float4 l0, l1;
    l0.x = tf32f((v0.x - mu) * rsd * w0.x + b0.x);
    l0.y = tf32f((v0.y - mu) * rsd * w0.y + b0.y);
    l0.z = tf32f((v0.z - mu) * rsd * w0.z + b0.z);
    l0.w = tf32f((v0.w - mu) * rsd * w0.w + b0.w);
    l1.x = tf32f((v1.x - mu) * rsd * w1.x + b1.x);
    l1.y = tf32f((v1.y - mu) * rsd * w1.y + b1.y);
    l1.z = tf32f((v1.z - mu) * rsd * w1.z + b1.z);
    l1.w = tf32f((v1.w - mu) * rsd * w1.w + b1.w);
    float4* outr = (float4*)(n1 + row * C_);
    outr[lane] = l0; outr[lane + 32] = l1;
}

// ---------------- q kernel: LN(x2) -> softmax q (tf32) + raw exp qe (tf32) ----
__global__ void q_kernel(const float* __restrict__ x,
                         const float* __restrict__ w,
                         const float* __restrict__ b,
                         float* __restrict__ qout,
                         float* __restrict__ qeout) {
    int warp = threadIdx.x >> 5, lane = threadIdx.x & 31;
    size_t row = (size_t)blockIdx.x * 8 + warp;
    const float4* xr = (const float4*)(x + row * C_);
    float4 v0 = xr[lane], v1 = xr[lane + 32];
    float s  = v0.x + v0.y + v0.z + v0.w + v1.x + v1.y + v1.z + v1.w;
    float s2 = v0.x*v0.x + v0.y*v0.y + v0.z*v0.z + v0.w*v0.w
             + v1.x*v1.x + v1.y*v1.y + v1.z*v1.z + v1.w*v1.w;
    #pragma unroll
    for (int o = 16; o > 0; o >>= 1) {
        s  += __shfl_xor_sync(0xffffffffu, s, o);
        s2 += __shfl_xor_sync(0xffffffffu, s2, o);
    }
    float mu = s * (1.f / C_);
    float rsd = rsqrtf(s2 * (1.f / C_) - mu * mu + LN_EPS);
    float4 w0 = ((const float4*)w)[lane], w1 = ((const float4*)w)[lane + 32];
    float4 b0 = ((const float4*)b)[lane], b1 = ((const float4*)b)[lane + 32];
    float4 e0, e1;
    e0.x = fexp((v0.x - mu) * rsd * w0.x + b0.x);
    e0.y = fexp((v0.y - mu) * rsd * w0.y + b0.y);
    e0.z = fexp((v0.z - mu) * rsd * w0.z + b0.z);
    e0.w = fexp((v0.w - mu) * rsd * w0.w + b0.w);
    e1.x = fexp((v1.x - mu) * rsd * w1.x + b1.x);
    e1.y = fexp((v1.y - mu) * rsd * w1.y + b1.y);
    e1.z = fexp((v1.z - mu) * rsd * w1.z + b1.z);
    e1.w = fexp((v1.w - mu) * rsd * w1.w + b1.w);
    float se = e0.x + e0.y + e0.z + e0.w + e1.x + e1.y + e1.z + e1.w;
    #pragma unroll
    for (int o = 16; o > 0; o >>= 1) se += __shfl_xor_sync(0xffffffffu, se, o);
    float inv = 1.f / se;
    float4* qer = (float4*)(qeout + row * C_);
    float4 t0, t1;
    t0.x = tf32f(e0.x); t0.y = tf32f(e0.y); t0.z = tf32f(e0.z); t0.w = tf32f(e0.w);
    t1.x = tf32f(e1.x); t1.y = tf32f(e1.y); t1.z = tf32f(e1.z); t1.w = tf32f(e1.w);
    qer[lane] = t0; qer[lane + 32] = t1;
    float4 u0, u1;
    u0.x = tf32f(e0.x * inv); u0.y = tf32f(e0.y * inv);
    u0.z = tf32f(e0.z * inv); u0.w = tf32f(e0.w * inv);
    u1.x = tf32f(e1.x * inv); u1.y = tf32f(e1.y * inv);
    u1.z = tf32f(e1.z * inv); u1.w = tf32f(e1.w * inv);
    float4* qr = (float4*)(qout + row * C_);
    qr[lane] = u0; qr[lane + 32] = u1;
}

// ---------------- zero + column sum (S) ---------------------------------------
__global__ void zero_kernel(float* __restrict__ p, int n) {
    int i = blockIdx.x * 256 + threadIdx.x;
    if (i < n) p[i] = 0.f;
}
__global__ void colsum_kernel(const float* __restrict__ qe, float* __restrict__ S) {
    int b = blockIdx.y, ch = blockIdx.x, t = threadIdx.x;
    const float* base = qe + ((size_t)b * N_ + (size_t)ch * CR_) * C_ + t;
    float s = 0.f;
    for (int r = 0; r < CR_; r++) s += base[(size_t)r * C_];
    atomicAdd(&S[b * C_ + t], s);
}

// ---------------- context GEMM: pure tf32 mma, cp.async 3-stage ---------------
#define CSTAGEW (2 * 16 * 136)            // words per stage (sa+sb)
#define CSMEM   (3 * CSTAGEW * 4)         // 52224 B
__global__ __launch_bounds__(256) void ctx_gemm(
        const float* __restrict__ qe, const float* __restrict__ n1,
        float* __restrict__ ctxp) {
    extern __shared__ __align__(16) uint cpool[];
    int bz = blockIdx.z;
    int b = bz / KS_, sk = bz % KS_;
    int m0 = blockIdx.y * 128, n0 = blockIdx.x * 128;
    const float* A  = qe + (size_t)b * N_ * C_;
    const float* Bx = n1 + (size_t)b * N_ * C_;

    int t = threadIdx.x;
    int warp = t >> 5, lane = t & 31, g = lane >> 2, tg = lane & 3;
    int wm = (warp >> 2) * 64, wn = (warp & 3) * 32;
    int kk0 = t >> 5, kk1 = 8 + kk0, m4 = (t & 31) * 4;
    int kbase = sk * CHK_;
    uint abase = smem_u32(cpool);

    float4 acc[4][4];
    #pragma unroll
    for (int i = 0; i < 4; i++)
        #pragma unroll
        for (int j = 0; j < 4; j++) acc[i][j] = make_float4(0.f, 0.f, 0.f, 0.f);

    auto ISSUE = [&](int kt, int buf) {
        int r0 = kbase + kt * 16 + kk0, r1 = kbase + kt * 16 + kk1;
        uint base = abase + (uint)buf * (CSTAGEW * 4);
        cp16(base + (uint)(kk0 * 136 + m4) * 4, &A[(size_t)r0 * C_ + m0 + m4]);
        cp16(base + (uint)(kk1 * 136 + m4) * 4, &A[(size_t)r1 * C_ + m0 + m4]);
        cp16(base + (uint)(16 * 136 + kk0 * 136 + m4) * 4, &Bx[(size_t)r0 * C_ + n0 + m4]);
        cp16(base + (uint)(16 * 136 + kk1 * 136 + m4) * 4, &Bx[(size_t)r1 * C_ + n0 + m4]);
        CP_COMMIT();
    };

    const int NT = CHK_ / 16;   // 36
    ISSUE(0, 0);
    ISSUE(1, 1);
    for (int kt = 0; kt < NT; kt++) {
        // drain tail correctly: on the last stage no group may remain in flight
        if (kt < NT - 1) { CP_WAIT1(); } else { CP_WAIT0(); }
        __syncthreads();
        if (kt + 2 < NT) ISSUE(kt + 2, (kt + 2) % 3);
        const uint* sa = cpool + (kt % 3) * CSTAGEW;
        const uint* sb = sa + 16 * 136;
        #pragma unroll
        for (int ks = 0; ks < 16; ks += 8) {
            uint afr[4][4], bfr[4][2];
            #pragma unroll
            for (int mt = 0; mt < 4; mt++) {
                int m = wm + mt * 16 + g;
                afr[mt][0] = sa[(ks + tg) * 136 + m];
                afr[mt][1] = sa[(ks + tg) * 136 + m + 8];
                afr[mt][2] = sa[(ks + tg + 4) * 136 + m];
                afr[mt][3] = sa[(ks + tg + 4) * 136 + m + 8];
            }
            #pragma unroll
            for (int nt = 0; nt < 4; nt++) {
                int n = wn + nt * 8 + g;
                bfr[nt][0] = sb[(ks + tg) * 136 + n];
                bfr[nt][1] = sb[(ks + tg + 4) * 136 + n];
            }
            #pragma unroll
            for (int mt = 0; mt < 4; mt++)
                #pragma unroll
                for (int nt = 0; nt < 4; nt++)
                    mma8(acc[mt][nt], afr[mt], bfr[nt]);
        }
    }

    float* dst = ctxp + ((size_t)sk * B_ + b) * C_ * C_;
    #pragma unroll
    for (int mt = 0; mt < 4; mt++) {
        int row = m0 + wm + mt * 16 + g;
        #pragma unroll
        for (int nt = 0; nt < 4; nt++) {
            int col = n0 + wn + nt * 8 + tg * 2;
            *(float2*)&dst[(size_t)row * C_ + col] = make_float2(acc[mt][nt].x, acc[mt][nt].y);
            *(float2*)&dst[(size_t)(row + 8) * C_ + col] = make_float2(acc[mt][nt].z, acc[mt][nt].w);
        }
    }
}

// ---------------- combined 4-way top-k masked softmax ------------------------
__global__ void topk_kernel(const float* __restrict__ ctxp, float* __restrict__ ctx,
                            const float* __restrict__ aw, const float* __restrict__ Sg) {
    __shared__ float sc[C_];
    __shared__ float sh[8];
    int row = blockIdx.x;
    int b = row >> 8, d = row & 255;
    int t = threadIdx.x;
    float v = 0.f;
    #pragma unroll
    for (int sk = 0; sk < KS_; sk++)
        v += ctxp[(((size_t)sk * B_ + b) * C_ + d) * C_ + t];
    v /= Sg[row];
    sc[t] = v;
    __syncthreads();
    int rank = 0;
    #pragma unroll 8
    for (int f = 0; f < C_; f++) {
        float vf = sc[f];
        rank += (vf > v) || (vf == v && f < t);
    }
    float m = blkMax(v, sh);
    float e = fexp(v - m);
    float z1 = blkSum(rank < 128 ? e : 0.f, sh);
    float z2 = blkSum(rank < 170 ? e : 0.f, sh);
    float z3 = blkSum(rank < 192 ? e : 0.f, sh);
    float z4 = blkSum(rank < 204 ? e : 0.f, sh);
    float coeff = 0.f;
    if (rank < 128) coeff += aw[0] / z1;
    if (rank < 170) coeff += aw[1] / z2;
    if (rank < 192) coeff += aw[2] / z3;
    if (rank < 204) coeff += aw[3] / z4;
    ctx[(size_t)row * C_ + t] = e * coeff;
}

// ---------------- small GEMM (F1): WA = tf32(reproj_w @ A) --------------------
__global__ void gemm64(const float* __restrict__ A, const float* __restrict__ B,
                       float* __restrict__ C,
                       int K, size_t sA, size_t sB, size_t sC,
                       int lda, int ldb, int ldc) {
    int bz = blockIdx.z;
    const float* Ab = A + (size_t)bz * sA;
    const float* Bb = B + (size_t)bz * sB;
    float* Cb = C + (size_t)bz * sC;
    int m0 = blockIdx.y * 64, n0 = blockIdx.x * 64;
    __shared__ float sa[16][65];
    __shared__ float sb[16][64];
    int t = threadIdx.x;
    int tx = t % 16, ty = t / 16;
    int r_ld = t / 16, kk_lda = t % 16;
    int c_ld = t % 64, kk_ldb = t / 64;
    float acc[4][4] = {};
    for (int k0 = 0; k0 < K; k0 += 16) {
        __syncthreads();
        #pragma unroll
        for (int it = 0; it < 4; it++) {
            sa[kk_lda][r_ld + 16 * it] = Ab[(size_t)(m0 + r_ld + 16 * it) * lda + k0 + kk_lda];
            sb[kk_ldb + 4 * it][c_ld] = Bb[(size_t)(k0 + kk_ldb + 4 * it) * ldb + n0 + c_ld];
        }
        __syncthreads();
        #pragma unroll
        for (int kk = 0; kk < 16; kk++) {
            float av[4], bv[4];
            #pragma unroll
            for (int i = 0; i < 4; i++) av[i] = sa[kk][ty + 16 * i];
            #pragma unroll
            for (int j = 0; j < 4; j++) bv[j] = sb[kk][tx + 16 * j];
            #pragma unroll
            for (int i = 0; i < 4; i++)
                #pragma unroll
                for (int j = 0; j < 4; j++) acc[i][j] = fmaf(av[i], bv[j], acc[i][j]);
        }
    }
    #pragma unroll
    for (int i = 0; i < 4; i++)
        #pragma unroll
        for (int j = 0; j < 4; j++)
            Cb[(size_t)(m0 + ty + 16 * i) * ldc + n0 + tx + 16 * j] = tf32f(acc[i][j]);
}

// ---------------- final: rp = q @ WA^T, cp.async 3-stage + bias -> LN -> NCHW -
#define FSTAGEW ((64 + 512) * 8)          // words per k8 stage = 4608
#define FSMEM   (3 * FSTAGEW * 4)         // 55296 B
__global__ __launch_bounds__(512) void final_kernel(
        const float* __restrict__ q, const float* __restrict__ WA,
        const float* __restrict__ rbias, const float* __restrict__ w2g,
        const float* __restrict__ b2g, float* __restrict__ out) {
    extern __shared__ __align__(16) uint pool[];

    int bb = blockIdx.y;
    int n0 = blockIdx.x * 64;
    const float* qb  = q  + (size_t)bb * N_ * C_ + (size_t)n0 * C_;
    const float* WAb = WA + (size_t)bb * O_ * C_;

    int t = threadIdx.x, warp = t >> 5, lane = t & 31, g = lane >> 2, tg = lane & 3;
    int o0 = warp * 32;
    uint abase = smem_u32(pool);

    float4 acc[4][4];
    #pragma unroll
    for (int i = 0; i < 4; i++)
        #pragma unroll
        for (int j = 0; j < 4; j++) acc[i][j] = make_float4(0.f, 0.f, 0.f, 0.f);

    auto ISSUE = [&](int kt, int buf) {
        int k0 = kt * 8;
        uint base = abase + (uint)buf * (FSTAGEW * 4);
        #pragma unroll
        for (int i = 0; i < 3; i++) {
            int c = t + 512 * i;
            if (i < 2 || t < 128) {
                int row = c >> 1, half = c & 1;
                const float* src = (row < 64)
                    ? &qb[(size_t)row * C_ + k0 + half * 4]
                    : &WAb[(size_t)(row - 64) * C_ + k0 + half * 4];
                cp16(base + (uint)(row * 8 + half * 4) * 4, src);
            }
        }
        CP_COMMIT();
    };

    const int NT = C_ / 8;   // 32
    ISSUE(0, 0);
    ISSUE(1, 1);
    for (int kt = 0; kt < NT; kt++) {
        if (kt < NT - 1) { CP_WAIT1(); } else { CP_WAIT0(); }
        __syncthreads();
        if (kt + 2 < NT) ISSUE(kt + 2, (kt + 2) % 3);
        const uint* sq  = pool + (kt % 3) * FSTAGEW;
        const uint* swa = sq + 64 * 8;
        uint afr[4][4], bfr[4][2];
        #pragma unroll
        for (int mt = 0; mt < 4; mt++) {
            int r1 = mt * 16 + g;
            afr[mt][0] = sq[r1 * 8 + tg];
            afr[mt][1] = sq[(r1 + 8) * 8 + tg];
            afr[mt][2] = sq[r1 * 8 + tg + 4];
            afr[mt][3] = sq[(r1 + 8) * 8 + tg + 4];
        }
        #pragma unroll
        for (int nt = 0; nt < 4; nt++) {
            int o = o0 + nt * 8 + g;
            bfr[nt][0] = swa[o * 8 + tg];
            bfr[nt][1] = swa[o * 8 + tg + 4];
        }
        #pragma unroll
        for (int mt = 0; mt < 4; mt++)
            #pragma unroll
            for (int nt = 0; nt < 4; nt++)
                mma8(acc[mt][nt], afr[mt], bfr[nt]);
    }
    __syncthreads();

    // ---- epilogue (pool reused) ----
    float* redS = (float*)pool;            // [16][64]
    float* redQ = (float*)(pool + 1024);   // [16][64]
    float* muS  = (float*)(pool + 2048);   // [64]
    float* rsS  = (float*)(pool + 2112);   // [64]
    float* sout = (float*)(pool + 2176);   // [128][68]

    #pragma unroll
    for (int nt = 0; nt < 4; nt++) {
        int o = o0 + nt * 8 + tg * 2;
        float2 rb = *(const float2*)&rbias[o];
        #pragma unroll
        for (int mt = 0; mt < 4; mt++) {
            acc[mt][nt].x += rb.x; acc[mt][nt].y += rb.y;
            acc[mt][nt].z += rb.x; acc[mt][nt].w += rb.y;
        }
    }

    #pragma unroll
    for (int mt = 0; mt < 4; mt++) {
        float sA = 0.f, qA = 0.f, sB = 0.f, qB = 0.f;
        #pragma unroll
        for (int nt = 0; nt < 4; nt++) {
            float4 a = acc[mt][nt];
            sA += a.x + a.y; qA += a.x * a.x + a.y * a.y;
            sB += a.z + a.w; qB += a.z * a.z + a.w * a.w;
        }
        #pragma unroll
        for (int o = 1; o <= 2; o <<= 1) {
            sA += __shfl_xor_sync(0xffffffffu, sA, o);
            qA += __shfl_xor_sync(0xffffffffu, qA, o);
            sB += __shfl_xor_sync(0xffffffffu, sB, o);
            qB += __shfl_xor_sync(0xffffffffu, qB, o);
        }
        if (tg == 0) {
            redS[warp * 64 + mt * 16 + g] = sA;
            redQ[warp * 64 + mt * 16 + g] = qA;
            redS[warp * 64 + mt * 16 + g + 8] = sB;
            redQ[warp * 64 + mt * 16 + g + 8] = qB;
        }
    }
    __syncthreads();
    if (t < 64) {
        float s = 0.f, qq = 0.f;
        #pragma unroll
        for (int w = 0; w < 16; w++) { s += redS[w * 64 + t]; qq += redQ[w * 64 + t]; }
        float mu = s * (1.f / O_);
        float var = qq * (1.f / O_) - mu * mu;
        muS[t] = mu;
        rsS[t] = rsqrtf(var + LN_EPS);
    }
    __syncthreads();
    float mu1[4], rs1[4], mu2[4], rs2[4];
    #pragma unroll
    for (int mt = 0; mt < 4; mt++) {
        mu1[mt] = muS[mt * 16 + g];     rs1[mt] = rsS[mt * 16 + g];
        mu2[mt] = muS[mt * 16 + g + 8]; rs2[mt] = rsS[mt * 16 + g + 8];
    }
    __syncthreads();

    #pragma unroll
    for (int p = 0; p < 4; p++) {
        if ((warp >> 2) == p) {
            int obase = (warp & 3) * 32;
            #pragma unroll
            for (int nt = 0; nt < 4; nt++) {
                int ol = obase + nt * 8 + tg * 2;
                int o = p * 128 + ol;
                float2 wv = *(const float2*)&w2g[o];
                float2 bv = *(const float2*)&b2g[o];
                #pragma unroll
                for (int mt = 0; mt < 4; mt++) {
                    int r1 = mt * 16 + g, r2 = r1 + 8;
                    float4 a = acc[mt][nt];
                    sout[ol * 68 + r1]       = (a.x - mu1[mt]) * rs1[mt] * wv.x + bv.x;
                    sout[(ol + 1) * 68 + r1] = (a.y - mu1[mt]) * rs1[mt] * wv.y + bv.y;
                    sout[ol * 68 + r2]       = (a.z - mu2[mt]) * rs2[mt] * wv.x + bv.x;
                    sout[(ol + 1) * 68 + r2] = (a.w - mu2[mt]) * rs2[mt] * wv.y + bv.y;
                }
            }
        }
        __syncthreads();
        #pragma unroll
        for (int i = 0; i < 4; i++) {
            int idx = t + 512 * i;
            int ol = idx >> 4, nn = (idx & 15) * 4;
            float4 v = *(float4*)&sout[ol * 68 + nn];
            *(float4*)&out[((size_t)bb * O_ + p * 128 + ol) * N_ + n0 + nn] = v;
        }
        __syncthreads();
    }
}

// ---------------- launch -----------------------------------------------------
extern "C" void kernel_launch(void* const* d_in, const int* in_sizes, int n_in,
                              void* d_out, int out_size) {
    const float* x1       = (const float*)d_in[0];
    const float* x2       = (const float*)d_in[1];
    const float* norm1_w  = (const float*)d_in[2];
    const float* norm1_b  = (const float*)d_in[3];
    const float* reproj_w = (const float*)d_in[4];
    const float* reproj_b = (const float*)d_in[5];
    const float* norm2_w  = (const float*)d_in[6];
    const float* norm2_b  = (const float*)d_in[7];
    const float* attn_w   = (const float*)d_in[8];
    float* out = (float*)d_out;

    float *q, *qe, *n1, *S, *ctxp, *ctx, *WA;
    cudaGetSymbolAddress((void**)&q,    g_q);
    cudaGetSymbolAddress((void**)&qe,   g_qe);
    cudaGetSymbolAddress((void**)&n1,   g_n1);
    cudaGetSymbolAddress((void**)&S,    g_S);
    cudaGetSymbolAddress((void**)&ctxp, g_ctxp);
    cudaGetSymbolAddress((void**)&ctx,  g_ctx);
    cudaGetSymbolAddress((void**)&WA,   g_WA);

    cudaFuncSetAttribute(ctx_gemm,
                         cudaFuncAttributeMaxDynamicSharedMemorySize, CSMEM);
    cudaFuncSetAttribute(final_kernel,
                         cudaFuncAttributeMaxDynamicSharedMemorySize, FSMEM);

    ln1_kernel<<<B_ * N_ / 8, 256>>>(x1, norm1_w, norm1_b, n1);
    q_kernel<<<B_ * N_ / 8, 256>>>(x2, norm1_w, norm1_b, q, qe);
    zero_kernel<<<(B_ * C_ + 255) / 256, 256>>>(S, B_ * C_);
    colsum_kernel<<<dim3(NCH_, B_), 256>>>(qe, S);

    ctx_gemm<<<dim3(2, 2, B_ * KS_), 256, CSMEM>>>(qe, n1, ctxp);

    topk_kernel<<<B_ * C_, 256>>>(ctxp, ctx, attn_w, S);

    gemm64<<<dim3(C_ / 64, O_ / 64, B_), 256>>>(
        reproj_w, ctx, WA, C_,
        (size_t)0, (size_t)C_ * C_, (size_t)O_ * C_,
        C_, C_, C_);

    final_kernel<<<dim3(N_ / 64, B_), 512, FSMEM>>>(
        q, WA, reproj_b, norm2_w, norm2_b, out);
}